// round 1
// baseline (speedup 1.0000x reference)
#include <cuda_runtime.h>
#include <cuda_bf16.h>
#include <math.h>

// Problem constants
#define B_   128
#define T_   20
#define D_   512
#define H_   512
#define V_   32000
#define NCLS 1000
#define TOPK 5
#define BN_EPS 1e-5f

// ---------------- scratch (device globals; no allocation allowed) ----------
__device__ float d_cls[B_ * D_];            // (B, D)
__device__ float d_proj[B_ * D_];           // (B, D)  (BN applied in place)
__device__ float d_X[B_ * T_ * D_];         // (B*T, D) GRU inputs
__device__ float d_GI[B_ * T_ * 3 * H_];    // (B*T, 3H) input-gate preacts
__device__ float d_GH[B_ * 3 * H_];         // (B, 3H)  per-step hidden preacts
__device__ float d_h[B_ * H_];              // (B, H)   GRU state
__device__ float d_feats[B_ * T_ * 2 * H_]; // (B*T, 2H): [out | ct]
__device__ float d_u[B_ * T_ * H_];         // (B*T, H) = out @ attn_W
__device__ float d_attn_WT[H_ * H_];        // attn_W transposed

// ---------------- helpers ---------------------------------------------------
__device__ __forceinline__ float tf32r(float x) {
    unsigned y;
    asm("cvt.rna.tf32.f32 %0, %1;" : "=r"(y) : "f"(x));
    return __uint_as_float(y);
}

__device__ __forceinline__ void mma_tf32(float* c, const unsigned* a, const unsigned* b) {
    asm volatile(
        "mma.sync.aligned.m16n8k8.row.col.f32.tf32.tf32.f32 "
        "{%0,%1,%2,%3}, {%4,%5,%6,%7}, {%8,%9}, {%0,%1,%2,%3};"
        : "+f"(c[0]), "+f"(c[1]), "+f"(c[2]), "+f"(c[3])
        : "r"(a[0]), "r"(a[1]), "r"(a[2]), "r"(a[3]), "r"(b[0]), "r"(b[1]));
}

__device__ __forceinline__ float sigmoidf_(float x) { return 1.0f / (1.0f + expf(-x)); }

// ---------------- generic C = A @ B^T (+bias) in TF32 -----------------------
// A: (M,K) row-major lda; B: (N,K) row-major ldb; C: (M,N) ldc.
// Requires M%128==0, N%128==0, K%32==0 (all shapes here satisfy this).
__global__ void __launch_bounds__(256) gemm_tf32_kernel(
    const float* __restrict__ A, int lda,
    const float* __restrict__ B, int ldb,
    const float* __restrict__ bias,
    float* __restrict__ C, int ldc,
    int M, int N, int K)
{
    __shared__ float As[128][36];
    __shared__ float Bs[128][36];

    const int bm = blockIdx.y * 128;
    const int bn = blockIdx.x * 128;
    const int tid  = threadIdx.x;
    const int warp = tid >> 5;
    const int lane = tid & 31;
    const int wm = (warp >> 1) * 32;   // 4 warps over M (32 rows each)
    const int wn = (warp & 1) * 64;    // 2 warps over N (64 cols each)
    const int g  = lane >> 2;          // group row 0..7
    const int tg = lane & 3;           // thread-in-group 0..3

    float acc[2][8][4];
#pragma unroll
    for (int i = 0; i < 2; i++)
#pragma unroll
        for (int j = 0; j < 8; j++)
#pragma unroll
            for (int k = 0; k < 4; k++) acc[i][j][k] = 0.0f;

    for (int k0 = 0; k0 < K; k0 += 32) {
        // load A tile 128x32 (as float4), convert to tf32 rounding
#pragma unroll
        for (int i = tid; i < 1024; i += 256) {
            int r  = i >> 3;
            int c4 = (i & 7) * 4;
            float4 v = *(const float4*)(A + (size_t)(bm + r) * lda + k0 + c4);
            As[r][c4 + 0] = tf32r(v.x);
            As[r][c4 + 1] = tf32r(v.y);
            As[r][c4 + 2] = tf32r(v.z);
            As[r][c4 + 3] = tf32r(v.w);
        }
#pragma unroll
        for (int i = tid; i < 1024; i += 256) {
            int r  = i >> 3;
            int c4 = (i & 7) * 4;
            float4 v = *(const float4*)(B + (size_t)(bn + r) * ldb + k0 + c4);
            Bs[r][c4 + 0] = tf32r(v.x);
            Bs[r][c4 + 1] = tf32r(v.y);
            Bs[r][c4 + 2] = tf32r(v.z);
            Bs[r][c4 + 3] = tf32r(v.w);
        }
        __syncthreads();

#pragma unroll
        for (int kk = 0; kk < 32; kk += 8) {
            unsigned a[2][4], bfr[8][2];
#pragma unroll
            for (int mi = 0; mi < 2; mi++) {
                int r = wm + mi * 16 + g;
                a[mi][0] = __float_as_uint(As[r][kk + tg]);
                a[mi][1] = __float_as_uint(As[r + 8][kk + tg]);
                a[mi][2] = __float_as_uint(As[r][kk + tg + 4]);
                a[mi][3] = __float_as_uint(As[r + 8][kk + tg + 4]);
            }
#pragma unroll
            for (int ni = 0; ni < 8; ni++) {
                int c = wn + ni * 8 + g;
                bfr[ni][0] = __float_as_uint(Bs[c][kk + tg]);
                bfr[ni][1] = __float_as_uint(Bs[c][kk + tg + 4]);
            }
#pragma unroll
            for (int mi = 0; mi < 2; mi++)
#pragma unroll
                for (int ni = 0; ni < 8; ni++)
                    mma_tf32(acc[mi][ni], a[mi], bfr[ni]);
        }
        __syncthreads();
    }

    // epilogue
#pragma unroll
    for (int mi = 0; mi < 2; mi++) {
#pragma unroll
        for (int ni = 0; ni < 8; ni++) {
            int row0 = bm + wm + mi * 16 + g;
            int col0 = bn + wn + ni * 8 + tg * 2;
            float bs0 = bias ? bias[col0]     : 0.0f;
            float bs1 = bias ? bias[col0 + 1] : 0.0f;
            C[(size_t)row0 * ldc + col0]           = acc[mi][ni][0] + bs0;
            C[(size_t)row0 * ldc + col0 + 1]       = acc[mi][ni][1] + bs1;
            C[(size_t)(row0 + 8) * ldc + col0]     = acc[mi][ni][2] + bs0;
            C[(size_t)(row0 + 8) * ldc + col0 + 1] = acc[mi][ni][3] + bs1;
        }
    }
}

// ---------------- top-k(5) + class-embedding mean ---------------------------
__global__ void __launch_bounds__(256) topk_cls_kernel(
    const float* __restrict__ img, const float* __restrict__ cemb, float* __restrict__ cls)
{
    __shared__ float vals[NCLS];
    __shared__ float sval[256];
    __shared__ int   sidx[256];
    __shared__ int   win[TOPK];
    const int b = blockIdx.x, tid = threadIdx.x;

    for (int i = tid; i < NCLS; i += 256) vals[i] = img[b * NCLS + i];
    __syncthreads();

    for (int r = 0; r < TOPK; r++) {
        float bv = -INFINITY;
        int bi = NCLS;
        for (int i = tid; i < NCLS; i += 256) {
            float v = vals[i];
            if (v > bv || (v == bv && i < bi)) { bv = v; bi = i; }
        }
        sval[tid] = bv; sidx[tid] = bi;
        __syncthreads();
        for (int s = 128; s > 0; s >>= 1) {
            if (tid < s) {
                float ov = sval[tid + s]; int oi = sidx[tid + s];
                if (ov > sval[tid] || (ov == sval[tid] && oi < sidx[tid])) {
                    sval[tid] = ov; sidx[tid] = oi;
                }
            }
            __syncthreads();
        }
        if (tid == 0) { win[r] = sidx[0]; vals[sidx[0]] = -INFINITY; }
        __syncthreads();
    }

    for (int d = tid; d < D_; d += 256) {
        float s = 0.0f;
#pragma unroll
        for (int j = 0; j < TOPK; j++) s += cemb[(size_t)win[j] * D_ + d];
        cls[b * D_ + d] = s * 0.2f;
    }
}

// ---------------- batchnorm over batch dim (train mode, biased var) ---------
__global__ void __launch_bounds__(512) bn_kernel(
    float* __restrict__ proj, const float* __restrict__ gamma, const float* __restrict__ beta)
{
    const int d = threadIdx.x;
    float s = 0.0f, s2 = 0.0f;
    for (int b = 0; b < B_; b++) {
        float v = proj[b * D_ + d];
        s += v; s2 += v * v;
    }
    float mu  = s * (1.0f / B_);
    float var = s2 * (1.0f / B_) - mu * mu;
    float inv = rsqrtf(var + BN_EPS);
    float gm = gamma[d], bt = beta[d];
    for (int b = 0; b < B_; b++) {
        proj[b * D_ + d] = (proj[b * D_ + d] - mu) * inv * gm + bt;
    }
}

// ---------------- build GRU input matrix X (B*T, D) --------------------------
__global__ void __launch_bounds__(256) build_x_kernel(
    const float* __restrict__ proj, const float* __restrict__ emb,
    const int* __restrict__ targets, float* __restrict__ X)
{
    int idx = blockIdx.x * 256 + threadIdx.x;            // < 2560*512
    int row = idx >> 9;
    int d   = idx & 511;
    int b = row / T_, t = row % T_;
    float v;
    if (t == 0) v = proj[b * D_ + d];
    else {
        int tok = targets[b * T_ + (t - 1)];
        v = emb[(size_t)tok * D_ + d];
    }
    X[(size_t)row * D_ + d] = v;
}

// ---------------- zero h -----------------------------------------------------
__global__ void zero_h_kernel() {
    int idx = blockIdx.x * 256 + threadIdx.x;
    if (idx < B_ * H_) d_h[idx] = 0.0f;
}

// ---------------- GRU gate fusion (per timestep) -----------------------------
__global__ void __launch_bounds__(256) gate_kernel(
    const float* __restrict__ GI, const float* __restrict__ GH,
    float* __restrict__ h, float* __restrict__ feats,
    const int* __restrict__ real_lens, int t)
{
    int idx = blockIdx.x * 256 + threadIdx.x;            // < 128*512
    int b = idx >> 9;
    int j = idx & 511;
    const float* gi = GI + (size_t)(b * T_ + t) * (3 * H_);
    const float* gh = GH + (size_t)b * (3 * H_);
    float r = sigmoidf_(gi[j]           + gh[j]);
    float z = sigmoidf_(gi[H_ + j]      + gh[H_ + j]);
    float n = tanhf(gi[2 * H_ + j] + r * gh[2 * H_ + j]);
    float hp = h[idx];
    float hn = (1.0f - z) * n + z * hp;
    h[idx] = hn;
    float v = (t < real_lens[b]) ? hn : 0.0f;
    feats[(size_t)(b * T_ + t) * (2 * H_) + j] = v;       // left half = masked out
}

// ---------------- attn_W transpose -------------------------------------------
__global__ void __launch_bounds__(256) transpose_kernel(
    const float* __restrict__ W, float* __restrict__ WT)
{
    int idx = blockIdx.x * 256 + threadIdx.x;            // < 512*512
    int e = idx >> 9, d = idx & 511;
    WT[e * H_ + d] = W[d * H_ + e];
}

// ---------------- causal bilinear attention (per batch) ----------------------
__global__ void __launch_bounds__(256) attn_kernel(
    float* __restrict__ feats, const float* __restrict__ u)
{
    __shared__ float sc[T_][T_ + 1];
    const int b = blockIdx.x, tid = threadIdx.x;
    const int warp = tid >> 5, lane = tid & 31;
    const float* outb = feats + (size_t)b * T_ * (2 * H_);    // row stride 2H
    const float* ub   = u     + (size_t)b * T_ * H_;

    // scores[t][s] = <u[t], out[s]> for s < t  (190 pairs, warp per pair)
    for (int p = warp; p < (T_ * (T_ - 1)) / 2; p += 8) {
        int t = 1;
        while ((t + 1) * t / 2 <= p) t++;
        int s = p - t * (t - 1) / 2;
        float acc = 0.0f;
        for (int k = lane; k < H_; k += 32)
            acc += ub[t * H_ + k] * outb[(size_t)s * (2 * H_) + k];
#pragma unroll
        for (int off = 16; off > 0; off >>= 1)
            acc += __shfl_xor_sync(0xFFFFFFFF, acc, off);
        if (lane == 0) sc[t][s] = acc;
    }
    __syncthreads();

    // softmax over s < t (t=0 row: alpha = 0)
    if (tid >= 1 && tid < T_) {
        int t = tid;
        float mx = -INFINITY;
        for (int s = 0; s < t; s++) mx = fmaxf(mx, sc[t][s]);
        float sum = 0.0f;
        for (int s = 0; s < t; s++) { float e = expf(sc[t][s] - mx); sc[t][s] = e; sum += e; }
        float inv = 1.0f / sum;
        for (int s = 0; s < t; s++) sc[t][s] *= inv;
    }
    __syncthreads();

    // ct[t][h] = sum_{s<t} alpha[t][s] * out[s][h]; write into feats right half
    for (int idx = tid; idx < T_ * H_; idx += 256) {
        int t = idx >> 9;
        int hh = idx & 511;
        float acc = 0.0f;
        for (int s = 0; s < t; s++)
            acc += sc[t][s] * outb[(size_t)s * (2 * H_) + hh];
        feats[(size_t)b * T_ * (2 * H_) + (size_t)t * (2 * H_) + H_ + hh] = acc;
    }
}

// ---------------- launch -----------------------------------------------------
extern "C" void kernel_launch(void* const* d_in, const int* in_sizes, int n_in,
                              void* d_out, int out_size)
{
    (void)in_sizes; (void)n_in; (void)out_size;
    const float* img_rep   = (const float*)d_in[0];
    const int*   targets   = (const int*)d_in[1];
    const int*   real_lens = (const int*)d_in[2];
    const float* class_emb = (const float*)d_in[3];
    const float* proj_W    = (const float*)d_in[4];
    const float* proj_b    = (const float*)d_in[5];
    const float* bn_gamma  = (const float*)d_in[6];
    const float* bn_beta   = (const float*)d_in[7];
    const float* emb_table = (const float*)d_in[8];
    const float* gru_Wih   = (const float*)d_in[9];
    const float* gru_Whh   = (const float*)d_in[10];
    const float* gru_bih   = (const float*)d_in[11];
    const float* gru_bhh   = (const float*)d_in[12];
    const float* attn_W    = (const float*)d_in[13];
    const float* vocab_W   = (const float*)d_in[14];
    const float* vocab_b   = (const float*)d_in[15];
    float* out = (float*)d_out;

    float *cls, *proj, *X, *GI, *GH, *h, *feats, *u, *attn_WT;
    cudaGetSymbolAddress((void**)&cls,     d_cls);
    cudaGetSymbolAddress((void**)&proj,    d_proj);
    cudaGetSymbolAddress((void**)&X,       d_X);
    cudaGetSymbolAddress((void**)&GI,      d_GI);
    cudaGetSymbolAddress((void**)&GH,      d_GH);
    cudaGetSymbolAddress((void**)&h,       d_h);
    cudaGetSymbolAddress((void**)&feats,   d_feats);
    cudaGetSymbolAddress((void**)&u,       d_u);
    cudaGetSymbolAddress((void**)&attn_WT, d_attn_WT);

    // image -> class embedding mean
    topk_cls_kernel<<<B_, 256>>>(img_rep, class_emb, cls);

    // proj = cls @ proj_W^T + proj_b   (128, 512, K=512)
    gemm_tf32_kernel<<<dim3(D_ / 128, B_ / 128), 256>>>(
        cls, D_, proj_W, D_, proj_b, proj, D_, B_, D_, D_);

    // batchnorm (train mode) in place
    bn_kernel<<<1, D_>>>(proj, bn_gamma, bn_beta);

    // build X (B*T, D)
    build_x_kernel<<<(B_ * T_ * D_) / 256, 256>>>(proj, emb_table, targets, X);

    // GI = X @ Wih^T + bih   (2560, 1536, K=512)
    gemm_tf32_kernel<<<dim3((3 * H_) / 128, (B_ * T_) / 128), 256>>>(
        X, D_, gru_Wih, D_, gru_bih, GI, 3 * H_, B_ * T_, 3 * H_, D_);

    // transpose attn_W (independent; do early)
    transpose_kernel<<<(H_ * H_) / 256, 256>>>(attn_W, attn_WT);

    // GRU recurrence
    zero_h_kernel<<<(B_ * H_ + 255) / 256, 256>>>();
    for (int t = 0; t < T_; t++) {
        gemm_tf32_kernel<<<dim3((3 * H_) / 128, B_ / 128), 256>>>(
            h, H_, gru_Whh, H_, gru_bhh, GH, 3 * H_, B_, 3 * H_, H_);
        gate_kernel<<<(B_ * H_) / 256, 256>>>(GI, GH, h, feats, real_lens, t);
    }

    // u = out @ attn_W  (via attn_W^T; A rows live in feats left half, lda=2H)
    gemm_tf32_kernel<<<dim3(H_ / 128, (B_ * T_) / 128), 256>>>(
        feats, 2 * H_, attn_WT, H_, nullptr, u, H_, B_ * T_, H_, H_);

    // causal attention -> ct into feats right half
    attn_kernel<<<B_, 256>>>(feats, u);

    // logits = feats @ vocab_W^T + vocab_b  (2560, 32000, K=1024)
    gemm_tf32_kernel<<<dim3(V_ / 128, (B_ * T_) / 128), 256>>>(
        feats, 2 * H_, vocab_W, 2 * H_, vocab_b, out, V_, B_ * T_, V_, 2 * H_);
}